// round 10
// baseline (speedup 1.0000x reference)
#include <cuda_runtime.h>
#include <cstdint>

// MultiLIF: I[B=32, L=2048, K=512] -> (spikes[B,L,K], spike_series[B,L,K])
// d_out: spikes (B*L*K floats) then spike_series.
//
// R10 = R9 (warp specialization) with a hang-proof barrier structure:
// ONE textual __syncthreads(), executed NBATCH+1 times by every thread.
// Pipelined schedule per iteration i: compute warps produce batch i,
// writer warps consume batch i-1, then the single barrier. Double-buffered
// mask slots keep producer/consumer one batch apart.
//
// Roles: warps 0-3 run the LIF recurrence and export spike bitmasks
// (__ballot -> STS); warps 4-7 reconstruct s (exact {0,1}), accumulate n
// (exact small-int float adds == reference), and issue both STGs.
// 128 blocks x 256 thr -> per SMSP: 1 compute + 1 writer warp, 128 SMs.

static constexpr int B_ = 32;
static constexpr int L_ = 2048;
static constexpr int K_ = 512;
static constexpr int UNROLL = 8;             // timesteps per batch
static constexpr int NBUF = 4;               // input ring depth (compute role)
static constexpr int NBATCH = L_ / UNROLL;   // 256
static constexpr int STRIDE = UNROLL * K_;
static constexpr int CW = 4;                 // compute warps per block
static constexpr int NEUR_PER_BLOCK = CW * 32;              // 128
static constexpr int NBLOCKS = (B_ * K_) / NEUR_PER_BLOCK;  // 128

__device__ __forceinline__ float div_const_rn(float x, float b, float y)
{
    // Markstein: correctly-rounded RN(x/b), y = RN(1/b). Branch-free;
    // == __fdiv_rn for all values reachable here.
    float q0 = __fmul_rn(x, y);
    float r  = __fmaf_rn(-b, q0, x);
    return __fmaf_rn(r, y, q0);
}

__global__ __launch_bounds__(2 * NEUR_PER_BLOCK, 1)
void MultiLIF_kernel(const float* __restrict__ I,
                     float* __restrict__ spikes,
                     float* __restrict__ series)
{
    __shared__ uint32_t masks[2][CW][UNROLL];   // [slot][compute warp][step]

    int tid = threadIdx.x;
    int wid = tid >> 5;
    int lid = tid & 31;
    bool is_compute = (wid < CW);
    int cw = is_compute ? wid : (wid - CW);

    int neuron = blockIdx.x * NEUR_PER_BLOCK + cw * 32 + lid;
    int b = neuron >> 9;
    int k = neuron & (K_ - 1);
    int64_t base = (int64_t)b * L_ * K_ + k;

    // ---- per-role state (registers only live on the taken path) ----
    const float* ip  = I + base;
    float*       sp  = spikes + base;
    float*       np  = series + base;
    const float c2 = -0.5f - div_const_rn(-0.5f, 20.0f, 0.05f);

    float buf[NBUF][UNROLL];
    const float* ipn = ip + (int64_t)(NBUF - 1) * STRIDE;
    float uv = 0.0f, a = 0.0f, n = 0.0f;
    bool fire = false;

    if (is_compute) {
        // prologue: preload batches 0..NBUF-2
#pragma unroll
        for (int p = 0; p < NBUF - 1; p++)
#pragma unroll
            for (int u = 0; u < UNROLL; u++)
                buf[p][u] = __ldcs(ip + (int64_t)(p * UNROLL + u) * K_);
    }

    // ---- unified pipelined loop: ONE textual barrier ----
#pragma unroll 1
    for (int i = 0; i <= NBATCH; i++) {
        if (is_compute) {
            if (i < NBATCH) {
                int p = i & (NBUF - 1);
                // prefetch batch i+NBUF-1 (past end -> safe address)
                const float* lp = (i + NBUF - 1 < NBATCH) ? ipn : ip;
#pragma unroll
                for (int u = 0; u < UNROLL; u++)
                    buf[(p + NBUF - 1) & (NBUF - 1)][u] = __ldcs(lp + u * K_);
                ipn += STRIDE;

                int slot = i & 1;
#pragma unroll
                for (int u = 0; u < UNROLL; u++) {
                    float It = buf[p][u];
                    float th = 1.0f + 1.5f * a;
                    float uA = (uv - div_const_rn(uv, 20.0f, 0.05f)) + It;
                    float uB = c2 + It;
                    float un = fire ? uB : uA;
                    bool f = (un >= th);
                    float s = f ? 1.0f : 0.0f;
                    unsigned m = __ballot_sync(0xFFFFFFFFu, f);
                    if (lid == 0) masks[slot][cw][u] = m;
                    a = (a - div_const_rn(a, 100.0f, 0.01f)) + s;
                    uv = un; fire = f;
                }
            }
        } else {
            if (i > 0) {
                int slot = (i - 1) & 1;
#pragma unroll
                for (int u = 0; u < UNROLL; u++) {
                    uint32_t m = masks[slot][cw][u];
                    float s = __uint_as_float(((m >> lid) & 1u) * 0x3F800000u);
                    n = n + s;
                    __stcs(sp + u * K_, s);
                    __stcs(np + u * K_, n);
                }
                sp += STRIDE; np += STRIDE;
            }
        }
        __syncthreads();   // single textual barrier, NBATCH+1 arrivals/thread
    }
}

extern "C" void kernel_launch(void* const* d_in, const int* in_sizes, int n_in,
                              void* d_out, int out_size)
{
    const float* I = (const float*)d_in[0];
    float* spikes = (float*)d_out;
    float* series = (float*)d_out + (int64_t)B_ * L_ * K_;

    dim3 block(2 * NEUR_PER_BLOCK);   // 256: 4 compute + 4 writer warps
    dim3 grid(NBLOCKS);               // 128 blocks -> 128 SMs
    MultiLIF_kernel<<<grid, block>>>(I, spikes, series);
}